// round 11
// baseline (speedup 1.0000x reference)
#include <cuda_runtime.h>
#include <cuda_bf16.h>

// NeuSSampler inverse-CDF importance sampling — v10 pair-table + SWAR select.
// weights [R,128,1] f32, existing_bins [R,129] f32, nears [R,1], fars [R,1]
// -> out [R,65] f32.  One warp per ray.
//
//  A) float4 weights + warp scan -> cdf c0..c4/lane (padding folded).
//  B) stage interleaved (cdf,bin) float2 pairs to smem (2x STS.128).
//  C) pack interior query-boundaries m1..m3 = floor(65*c+0.5) as bytes (M).
//  D) per query: 5-step shfl ladder over chunk tops -> p; 1 shfl of M +
//     SWAR byte-compare -> r; idx = 4p+r; 2x LDS.64 endpoint fetch; lerp;
//     coalesced store. j=64 via ballot, lane 0 finishes.

#define S_SAMP 128
#define NB 65
#define HIST_PAD 1e-5f
#define EPS_V 1e-5f
#define WPB 8
#define NTHREADS (WPB * 32)
#define INV_NB (1.0f / 65.0f)
#define FULL 0xffffffffu

__global__ __launch_bounds__(NTHREADS)
void neus_sampler_kernel(const float* __restrict__ weights,
                         const float* __restrict__ ebins,
                         const float* __restrict__ nears,
                         const float* __restrict__ fars,
                         float* __restrict__ out,
                         int R)
{
    __shared__ __align__(16) float2 pair_sm[WPB][130];

    const int warp = threadIdx.x >> 5;
    const int lane = threadIdx.x & 31;
    const unsigned ray = blockIdx.x * WPB + warp;
    if (ray >= (unsigned)R) return;

    // ---- A0. start all global traffic early (32-bit offsets) ----
    const int k = lane * 4;
    const float* ebrow = ebins + ray * 129u;
    const float4 wv = *reinterpret_cast<const float4*>(weights + ray * 128u + k);
    const float b0 = __ldg(ebrow + k);
    const float b1 = __ldg(ebrow + k + 1);
    const float b2 = __ldg(ebrow + k + 2);
    const float b3 = __ldg(ebrow + k + 3);
    const float nearv = nears[ray];
    const float farv  = fars[ray];

    const float l0 = wv.x;
    const float l1 = l0 + wv.y;
    const float l2 = l1 + wv.z;
    const float l3 = l2 + wv.w;

    // ---- A1. warp inclusive scan over chunk sums ----
    float pre = l3;
    #pragma unroll
    for (int off = 1; off < 32; off <<= 1) {
        float v = __shfl_up_sync(FULL, pre, off);
        if (lane >= off) pre += v;
    }
    const float total_raw = __shfl_sync(FULL, pre, 31);
    const float excl      = pre - l3;

    const float total_wp = total_raw + (float)S_SAMP * HIST_PAD;
    const float padding  = fmaxf(0.0f, EPS_V - total_wp);
    const float inv_wsum = __fdividef(1.0f, total_wp + padding);
    const float step     = HIST_PAD + padding * (1.0f / (float)S_SAMP);

    const float kf = (float)k;
    const float c0 = fmaf(kf,        step, excl     ) * inv_wsum;
    const float c1 = fmaf(kf + 1.0f, step, excl + l0) * inv_wsum;
    const float c2 = fmaf(kf + 2.0f, step, excl + l1) * inv_wsum;
    const float c3 = fmaf(kf + 3.0f, step, excl + l2) * inv_wsum;
    const float c4 = fmaf(kf + 4.0f, step, excl + l3) * inv_wsum;

    // ---- C. packed interior boundaries (each in [0,65], fits a byte) ----
    const int m1 = __float2int_rd(fmaf(65.0f, c1, 0.5f));
    const int m2 = __float2int_rd(fmaf(65.0f, c2, 0.5f));
    const int m3 = __float2int_rd(fmaf(65.0f, c3, 0.5f));
    const unsigned M = (unsigned)m1 | ((unsigned)m2 << 8) | ((unsigned)m3 << 16);

    // ---- B. stage (cdf,bin) pair table ----
    float2* pw = pair_sm[warp];
    float4 pA; pA.x = c0; pA.y = b0; pA.z = c1; pA.w = b1;
    float4 pB; pB.x = c2; pB.y = b2; pB.z = c3; pB.w = b3;
    *reinterpret_cast<float4*>(pw + k)     = pA;
    *reinterpret_cast<float4*>(pw + k + 2) = pB;
    if (lane == 31) {
        float2 pl; pl.x = c4; pl.y = __ldg(ebrow + 128);
        pw[128] = pl;
    }
    __syncwarp(FULL);

    const float dfn = farv - nearv;
    float* orow = out + ray * 65u;

    // ---- D. dual interleaved ladder over chunk tops ----
    const float u0 = ((float)lane + 0.5f)  * INV_NB;
    const float u1 = ((float)lane + 32.5f) * INV_NB;

    int p0 = 0, p1 = 0;
    {   // shared first probe
        const float cs = __shfl_sync(FULL, c0, 16);
        if (cs <= u0) p0 = 16;
        if (cs <= u1) p1 = 16;
    }
    #pragma unroll
    for (int st = 8; st >= 1; st >>= 1) {
        const float a0 = __shfl_sync(FULL, c0, p0 + st);
        const float a1 = __shfl_sync(FULL, c0, p1 + st);
        if (a0 <= u0) p0 += st;
        if (a1 <= u1) p1 += st;
    }

    // SWAR sub-segment select: bit7 of each byte of ((J|0x80..)-M) = (j>=m)
    const unsigned M0 = __shfl_sync(FULL, M, p0);
    const unsigned M1 = __shfl_sync(FULL, M, p1);
    const unsigned J0 = (unsigned)lane        * 0x01010101u;
    const unsigned J1 = (unsigned)(lane + 32) * 0x01010101u;
    const int r0 = __popc(((J0 | 0x80808080u) - M0) & 0x00808080u);
    const int r1 = __popc(((J1 | 0x80808080u) - M1) & 0x00808080u);

    const int i0 = p0 * 4 + r0;
    const int i1 = p1 * 4 + r1;
    const float2 lo0 = pw[i0], hi0 = pw[i0 + 1];
    const float2 lo1 = pw[i1], hi1 = pw[i1 + 1];

    const float t0  = (u0 - lo0.x) * __fdividef(1.0f, hi0.x - lo0.x);
    const float t1  = (u1 - lo1.x) * __fdividef(1.0f, hi1.x - lo1.x);
    const float bb0 = fmaf(t0, hi0.y - lo0.y, lo0.y);
    const float bb1 = fmaf(t1, hi1.y - lo1.y, lo1.y);
    orow[lane]      = fmaf(bb0, dfn, nearv);
    orow[lane + 32] = fmaf(bb1, dfn, nearv);

    // ---- E. j = 64: uniform owner via ballot, lane 0 finishes ----
    {
        const float u = 64.5f * INV_NB;
        const unsigned msk = __ballot_sync(FULL, c0 <= u);   // lane0 always set
        const int pt = 31 - __clz(msk);
        const unsigned Mt = __shfl_sync(FULL, M, pt);
        if (lane == 0) {
            const unsigned Jt = 64u * 0x01010101u;
            const int rt = __popc(((Jt | 0x80808080u) - Mt) & 0x00808080u);
            const int it = pt * 4 + rt;
            const float2 lo = pw[it], hi = pw[it + 1];
            const float t  = (u - lo.x) * __fdividef(1.0f, hi.x - lo.x);
            const float bb = fmaf(t, hi.y - lo.y, lo.y);
            orow[64] = fmaf(bb, dfn, nearv);
        }
    }
}

extern "C" void kernel_launch(void* const* d_in, const int* in_sizes, int n_in,
                              void* d_out, int out_size) {
    const float* weights = (const float*)d_in[0];
    const float* ebins   = (const float*)d_in[1];
    const float* nears   = (const float*)d_in[2];
    const float* fars    = (const float*)d_in[3];
    float* out = (float*)d_out;

    const int R = in_sizes[2];  // nears has R elements
    const int grid = (R + WPB - 1) / WPB;
    neus_sampler_kernel<<<grid, NTHREADS>>>(weights, ebins, nears, fars, out, R);
}

// round 12
// speedup vs baseline: 1.1977x; 1.1977x over previous
#include <cuda_runtime.h>
#include <cuda_bf16.h>

// NeuSSampler inverse-CDF importance sampling — v12.
// weights [R,128,1] f32, existing_bins [R,129] f32, nears [R,1], fars [R,1]
// -> out [R,65] f32.  One warp per ray.
//
// Fetch-mechanism split (each validated in earlier rounds):
//   owner chunk p : 5-step shfl ladder over sorted chunk tops (conflict-free)
//   sub-segment r : SWAR byte-compare on packed boundaries (2 shfl + ALU)
//   cdf endpoints : 2 scalar LDS.32 from a cdf-only smem table
//   bin endpoints : 2 LDG from the (prefetched, L1-resident) ebins row
// All address math 32-bit. j=64 handled by lane 0 via one ballot.

#define S_SAMP 128
#define NB 65
#define HIST_PAD 1e-5f
#define EPS_V 1e-5f
#define WPB 8
#define NTHREADS (WPB * 32)
#define INV_NB (1.0f / 65.0f)
#define FULL 0xffffffffu

__global__ __launch_bounds__(NTHREADS)
void neus_sampler_kernel(const float* __restrict__ weights,
                         const float* __restrict__ ebins,
                         const float* __restrict__ nears,
                         const float* __restrict__ fars,
                         float* __restrict__ out,
                         int R)
{
    __shared__ __align__(16) float cdf_sm[WPB][132];

    const int warp = threadIdx.x >> 5;
    const int lane = threadIdx.x & 31;
    const unsigned ray = blockIdx.x * WPB + warp;
    if (ray >= (unsigned)R) return;

    // ---- A0. start global traffic early (32-bit offsets) ----
    const int k = lane * 4;
    const float* ebrow = ebins + ray * 129u;
    if (lane < 5) {  // warm the whole 516B row into L1
        asm volatile("prefetch.global.L1 [%0];" :: "l"(ebrow + lane * 32));
    }
    const float4 wv = *reinterpret_cast<const float4*>(weights + ray * 128u + k);
    const float nearv = nears[ray];
    const float farv  = fars[ray];

    const float l0 = wv.x;
    const float l1 = l0 + wv.y;
    const float l2 = l1 + wv.z;
    const float l3 = l2 + wv.w;

    // ---- A1. warp inclusive scan over chunk sums ----
    float pre = l3;
    #pragma unroll
    for (int off = 1; off < 32; off <<= 1) {
        float v = __shfl_up_sync(FULL, pre, off);
        if (lane >= off) pre += v;
    }
    const float total_raw = __shfl_sync(FULL, pre, 31);
    const float excl      = pre - l3;

    const float total_wp = total_raw + (float)S_SAMP * HIST_PAD;
    const float padding  = fmaxf(0.0f, EPS_V - total_wp);
    const float inv_wsum = __fdividef(1.0f, total_wp + padding);
    const float step     = HIST_PAD + padding * (1.0f / (float)S_SAMP);

    const float kf = (float)k;
    const float c0 = fmaf(kf,        step, excl     ) * inv_wsum;
    const float c1 = fmaf(kf + 1.0f, step, excl + l0) * inv_wsum;
    const float c2 = fmaf(kf + 2.0f, step, excl + l1) * inv_wsum;
    const float c3 = fmaf(kf + 3.0f, step, excl + l2) * inv_wsum;
    const float c4 = fmaf(kf + 4.0f, step, excl + l3) * inv_wsum;

    // ---- B. packed interior boundaries (bytes; validated SWAR form) ----
    const int m1 = __float2int_rd(fmaf(65.0f, c1, 0.5f));
    const int m2 = __float2int_rd(fmaf(65.0f, c2, 0.5f));
    const int m3 = __float2int_rd(fmaf(65.0f, c3, 0.5f));
    const unsigned M = (unsigned)m1 | ((unsigned)m2 << 8) | ((unsigned)m3 << 16);

    // ---- C. cdf-only smem table ----
    float* cw = cdf_sm[warp];
    float4 cv4; cv4.x = c0; cv4.y = c1; cv4.z = c2; cv4.w = c3;
    *reinterpret_cast<float4*>(cw + k) = cv4;
    if (lane == 31) cw[128] = c4;
    __syncwarp(FULL);

    const float dfn = farv - nearv;
    float* orow = out + ray * 65u;

    // ---- D. dual interleaved ladder over chunk tops (pos only) ----
    const float u0 = ((float)lane + 0.5f)  * INV_NB;
    const float u1 = ((float)lane + 32.5f) * INV_NB;

    int p0 = 0, p1 = 0;
    {   // shared first probe
        const float cs = __shfl_sync(FULL, c0, 16);
        if (cs <= u0) p0 = 16;
        if (cs <= u1) p1 = 16;
    }
    #pragma unroll
    for (int st = 8; st >= 1; st >>= 1) {
        const float a0 = __shfl_sync(FULL, c0, p0 + st);
        const float a1 = __shfl_sync(FULL, c0, p1 + st);
        if (a0 <= u0) p0 += st;
        if (a1 <= u1) p1 += st;
    }

    // ---- E. SWAR sub-segment select ----
    const unsigned M0 = __shfl_sync(FULL, M, p0);
    const unsigned M1 = __shfl_sync(FULL, M, p1);
    const unsigned J0 = (unsigned)lane        * 0x01010101u;
    const unsigned J1 = (unsigned)(lane + 32) * 0x01010101u;
    const int r0 = __popc(((J0 | 0x80808080u) - M0) & 0x00808080u);
    const int r1 = __popc(((J1 | 0x80808080u) - M1) & 0x00808080u);

    const int i0 = p0 * 4 + r0;
    const int i1 = p1 * 4 + r1;

    // cdf endpoints: scalar LDS; bin endpoints: L1-hit LDG
    const float clo0 = cw[i0],      chi0 = cw[i0 + 1];
    const float clo1 = cw[i1],      chi1 = cw[i1 + 1];
    const float blo0 = __ldg(ebrow + i0);
    const float bhi0 = __ldg(ebrow + i0 + 1);
    const float blo1 = __ldg(ebrow + i1);
    const float bhi1 = __ldg(ebrow + i1 + 1);

    const float t0  = (u0 - clo0) * __fdividef(1.0f, chi0 - clo0);
    const float t1  = (u1 - clo1) * __fdividef(1.0f, chi1 - clo1);
    const float bb0 = fmaf(t0, bhi0 - blo0, blo0);
    const float bb1 = fmaf(t1, bhi1 - blo1, blo1);
    orow[lane]      = fmaf(bb0, dfn, nearv);
    orow[lane + 32] = fmaf(bb1, dfn, nearv);

    // ---- F. j = 64: one ballot, lane 0 finishes ----
    {
        const float u = 64.5f * INV_NB;
        const unsigned msk = __ballot_sync(FULL, c0 <= u);   // lane0 always set
        const int pt = 31 - __clz(msk);
        const unsigned Mt = __shfl_sync(FULL, M, pt);
        if (lane == 0) {
            const unsigned Jt = 64u * 0x01010101u;
            const int rt = __popc(((Jt | 0x80808080u) - Mt) & 0x00808080u);
            const int it = pt * 4 + rt;
            const float clo = cw[it], chi = cw[it + 1];
            const float blo = __ldg(ebrow + it);
            const float bhi = __ldg(ebrow + it + 1);
            const float t  = (u - clo) * __fdividef(1.0f, chi - clo);
            const float bb = fmaf(t, bhi - blo, blo);
            orow[64] = fmaf(bb, dfn, nearv);
        }
    }
}

extern "C" void kernel_launch(void* const* d_in, const int* in_sizes, int n_in,
                              void* d_out, int out_size) {
    const float* weights = (const float*)d_in[0];
    const float* ebins   = (const float*)d_in[1];
    const float* nears   = (const float*)d_in[2];
    const float* fars    = (const float*)d_in[3];
    float* out = (float*)d_out;

    const int R = in_sizes[2];  // nears has R elements
    const int grid = (R + WPB - 1) / WPB;
    neus_sampler_kernel<<<grid, NTHREADS>>>(weights, ebins, nears, fars, out, R);
}